// round 11
// baseline (speedup 1.0000x reference)
#include <cuda_runtime.h>
#include <cstdint>

// CIC deposition: 10M particles -> 256^3 float grid.
// Round 11: bin particles by (cx,cy) into 65536 fixed-capacity bins (256
// slots, Poisson mean 152.6 -> overflow ~1e-16/bin; direct-deposit fallback
// keeps correctness anyway). Deposit with one warp per bin: all 32 lanes
// share the bin's 4 grid rows, so each warp-RED's lanes fall inside 1KB ->
// L1tex wavefronts per RED drop from ~32 to ~8. Tests the hypothesis that
// spread-REDG cost (1.29 cyc/lane) is wavefront-bound, not lane-bound.

static constexpr int   NC    = 256;
static constexpr float GMINF = -10.0f;
static constexpr float DXF   = (float)(20.0 / 255.0);

static constexpr int    NBINS = 256 * 256;
static constexpr int    SLOTS = 256;
__device__ __align__(16) float4 g_bins[(size_t)NBINS * SLOTS];  // 256MB
__device__ int g_cursor[NBINS];

__global__ void zero_kernel(float4* __restrict__ out, int n4) {
    int i = blockIdx.x * blockDim.x + threadIdx.x;
    if (i < n4) out[i] = make_float4(0.f, 0.f, 0.f, 0.f);
    if (i < NBINS) g_cursor[i] = 0;
}

__device__ __forceinline__ void red_v4p(float* p, float a, float b, float c, float d, int pred) {
    asm volatile(
        "{\n\t"
        ".reg .pred q;\n\t"
        "setp.ne.s32 q, %5, 0;\n\t"
        "@q red.global.add.v4.f32 [%0], {%1, %2, %3, %4};\n\t"
        "}"
        :: "l"(p), "f"(a), "f"(b), "f"(c), "f"(d), "r"(pred) : "memory");
}

__device__ __forceinline__ void red_v1p(float* p, float a, int pred) {
    asm volatile(
        "{\n\t"
        ".reg .pred q;\n\t"
        "setp.ne.s32 q, %2, 0;\n\t"
        "@q red.global.add.f32 [%0], %1;\n\t"
        "}"
        :: "l"(p), "f"(a), "r"(pred) : "memory");
}

// R2-style deposit from already-computed float indices (fx,fy,fz) and weight.
__device__ __forceinline__ void deposit_from(
    float fx, float fy, float fz, float w, float* __restrict__ grid)
{
    float ixf = floorf(fx), iyf = floorf(fy), izf = floorf(fz);
    int cx = (int)ixf, cy = (int)iyf, cz = (int)izf;

    if ((unsigned)cx > 255u || (unsigned)cy > 255u || (unsigned)cz > 255u) return;

    float ox = fx - ixf, oy = fy - iyf, oz = fz - izf;

    // corner weight = ((w * X) * Y) * Z (reference association)
    float wx0 = w * (1.0f - ox);
    float wx1 = w * ox;
    float y0 = 1.0f - oy, y1 = oy;
    float z0 = 1.0f - oz, z1 = oz;

    bool bx = cx < (NC - 1);
    bool by = cy < (NC - 1);

    int  m    = cz & 3;
    int  use4 = (m != 3);
    int  fb   = !use4;
    int  fb2  = fb & (cz < (NC - 1));
    float a0 = (m == 0) ? 1.0f : 0.0f;
    float a1 = (m == 1) ? 1.0f : 0.0f;
    float a2 = (m == 2) ? 1.0f : 0.0f;

    float* g  = grid + (((size_t)cx * NC + (size_t)cy) * NC + (size_t)cz);
    float* gq = g - m;
    const size_t SX = (size_t)NC * NC;
    const size_t SY = NC;

    #define DEPOSIT_ROW(base_off, rw)  do {                                   \
        float v0 = (rw) * z0;                                                 \
        float v1 = (rw) * z1;                                                 \
        float l0 = v0 * a0;                                                   \
        float l1 = fmaf(v1, a0, v0 * a1);                                     \
        float l2 = fmaf(v1, a1, v0 * a2);                                     \
        float l3 = v1 * a2;                                                   \
        red_v4p(gq + (base_off), l0, l1, l2, l3, use4);                       \
        red_v1p(g + (base_off), v0, fb);                                      \
        red_v1p(g + (base_off) + 1, v1, fb2);                                 \
    } while (0)

    DEPOSIT_ROW(0, wx0 * y0);
    if (by) DEPOSIT_ROW(SY, wx0 * y1);
    if (bx) {
        DEPOSIT_ROW(SX, wx1 * y0);
        if (by) DEPOSIT_ROW(SX + SY, wx1 * y1);
    }
    #undef DEPOSIT_ROW
}

__device__ __forceinline__ void scatter_one(
    float px, float py, float pz, float w, float* __restrict__ grid)
{
    // Match JAX float32 arithmetic: subtract then IEEE divide
    float fx = (px - GMINF) / DXF;
    float fy = (py - GMINF) / DXF;
    float fz = (pz - GMINF) / DXF;

    float ixf = floorf(fx), iyf = floorf(fy);
    int cx = (int)ixf, cy = (int)iyf;
    float izf = floorf(fz);
    int cz = (int)izf;

    if ((unsigned)cx > 255u || (unsigned)cy > 255u || (unsigned)cz > 255u) return;

    int bin = (cx << 8) | cy;
    int slot = atomicAdd(&g_cursor[bin], 1);
    if (slot < SLOTS) {
        float4 v = make_float4(fx, fy, fz, w);
        __stcs(&g_bins[(size_t)bin * SLOTS + slot], v);
    } else {
        // statistically never; keeps correctness unconditional
        deposit_from(fx, fy, fz, w, grid);
    }
}

__global__ void __launch_bounds__(256) scatter_kernel(
    const float* __restrict__ pos,
    const float* __restrict__ wgt,
    float* __restrict__ grid,
    int n)
{
    int t = blockIdx.x * blockDim.x + threadIdx.x;
    int base = 4 * t;
    if (base >= n) return;

    if (base + 3 < n) {
        const float4* p4 = (const float4*)pos + 3 * (size_t)t;
        float4 A = __ldcs(p4 + 0);
        float4 B = __ldcs(p4 + 1);
        float4 C = __ldcs(p4 + 2);
        float4 W = __ldcs((const float4*)wgt + t);

        scatter_one(A.x, A.y, A.z, W.x, grid);
        scatter_one(A.w, B.x, B.y, W.y, grid);
        scatter_one(B.z, B.w, C.x, W.z, grid);
        scatter_one(C.y, C.z, C.w, W.w, grid);
    } else {
        for (int i = base; i < n; i++) {
            float px = __ldcs(pos + 3 * (size_t)i + 0);
            float py = __ldcs(pos + 3 * (size_t)i + 1);
            float pz = __ldcs(pos + 3 * (size_t)i + 2);
            float w  = __ldcs(wgt + i);
            scatter_one(px, py, pz, w, grid);
        }
    }
}

// one warp per bin: lanes process slots lane, lane+32, ... — payload loads are
// fully coalesced; all lanes deposit into the same 4 grid rows (1KB windows).
__global__ void __launch_bounds__(256) deposit_kernel(float* __restrict__ grid) {
    int warp = blockIdx.x * 8 + (threadIdx.x >> 5);
    if (warp >= NBINS) return;
    int lane = threadIdx.x & 31;

    int count = g_cursor[warp];
    if (count > SLOTS) count = SLOTS;

    const float4* base = g_bins + (size_t)warp * SLOTS;
    for (int s = lane; s < count; s += 32) {
        float4 p = __ldcs(base + s);
        deposit_from(p.x, p.y, p.z, p.w, grid);
    }
}

extern "C" void kernel_launch(void* const* d_in, const int* in_sizes, int n_in,
                              void* d_out, int out_size) {
    const float* positions = (const float*)d_in[0];
    const float* weights   = (const float*)d_in[1];
    float* grid = (float*)d_out;

    int n_particles = in_sizes[1];  // weights element count = N

    // 1) zero output grid + bin cursors
    int n4 = out_size / 4;
    zero_kernel<<<(n4 + 255) / 256, 256>>>((float4*)grid, n4);

    // 2) bin particles by (cx,cy)
    int n_threads_total = (n_particles + 3) / 4;
    int threads = 256;
    int blocks = (n_threads_total + threads - 1) / threads;
    scatter_kernel<<<blocks, threads>>>(positions, weights, grid, n_particles);

    // 3) warp-per-bin coalesced deposit
    deposit_kernel<<<NBINS / 8, 256>>>(grid);
}

// round 12
// speedup vs baseline: 1.1541x; 1.1541x over previous
#include <cuda_runtime.h>
#include <cstdint>

// CIC deposition: 10M particles -> 256^3 float grid.
// Round 12: endgame around the proven laws:
//   * RED cost ~1.27-1.33 cyc/active lane, width- and locality-independent.
//   * Fixed-layout floor = 4.5 active lanes/particle (16B quad max).
//   * Atomic footprint must stay <= ~64MB (L2 cliff).
// So: R5's 2x2x2-permuted single-pass deposit (4.5 lanes, 64MB scratch) with
// overhead minimized: NO zero kernel (scratch is zero-initialized at module
// load; the depermute kernel re-zeroes every block after reading it, so the
// zero-invariant holds across graph replays), and deposit occupancy raised
// via __launch_bounds__(256,8) (R2 ran 1.265 cyc/lane at 81% occ vs R5's
// 1.33 at 69.8%).
// Permuted layout: block(X,Y,Z) = 8 floats, lane = (xbit<<2)|(ybit<<1)|zbit;
// quad = 16B half-block (one xbit).

static constexpr float GMINF = -10.0f;
static constexpr float DXF   = (float)(20.0 / 255.0);

static constexpr size_t NBLK = 128u * 128u * 128u;       // 2,097,152 blocks
__device__ __align__(32) float g_scratch[NBLK * 8];      // 64MB, zero at load

__device__ __forceinline__ void red_v4p(float* p, float a, float b, float c, float d, int pred) {
    asm volatile(
        "{\n\t"
        ".reg .pred q;\n\t"
        "setp.ne.s32 q, %5, 0;\n\t"
        "@q red.global.add.v4.f32 [%0], {%1, %2, %3, %4};\n\t"
        "}"
        :: "l"(p), "f"(a), "f"(b), "f"(c), "f"(d), "r"(pred) : "memory");
}

__device__ __forceinline__ void deposit_one(float px, float py_, float pz, float w)
{
    // Match JAX float32 arithmetic: subtract then IEEE divide
    float fx = (px  - GMINF) / DXF;
    float fy = (py_ - GMINF) / DXF;
    float fz = (pz  - GMINF) / DXF;

    float ixf = floorf(fx), iyf = floorf(fy), izf = floorf(fz);
    int cx = (int)ixf, cy = (int)iyf, cz = (int)izf;

    if ((unsigned)cx > 255u || (unsigned)cy > 255u || (unsigned)cz > 255u) return;

    float ox = fx - ixf, oy = fy - iyf, oz = fz - izf;

    // corner weight = ((w * X) * Y) * Z (reference association)
    float wx0 = w * (1.0f - ox);
    float wx1 = w * ox;
    float wy0 = 1.0f - oy, wy1 = oy;
    float wz0 = 1.0f - oz, wz1 = oz;

    int bx = cx & 1, by = cy & 1, bz = cz & 1;

    // per-dim (block-offset, bit) weights; dim-block 1 holds only bit 0
    float yw00 = by ? 0.0f : wy0, yw01 = by ? wy0 : wy1, yw10 = by ? wy1 : 0.0f;
    float zw00 = bz ? 0.0f : wz0, zw01 = bz ? wz0 : wz1, zw10 = bz ? wz1 : 0.0f;

    int pY = by & (cy < 255);
    int pZ = bz & (cz < 255);
    int pX = (!bx) | (cx < 255);      // second x-quad valid (same block or X+1)

    // yz lane products for the 4 (y-block, z-block) targets
    float m00 = yw00 * zw00, m01 = yw00 * zw01, m10 = yw01 * zw00, m11 = yw01 * zw01;
    float n00 = yw00 * zw10, n10 = yw01 * zw10;    // z-spill block
    float q00 = yw10 * zw00, q01 = yw10 * zw01;    // y-spill block
    float r00 = yw10 * zw10;                        // yz-spill block

    const size_t SX = 128u * 128u * 8u;
    const size_t SY = 128u * 8u;
    const size_t SZ = 8u;

    #pragma unroll
    for (int k = 0; k < 2; k++) {
        int xc   = cx + k;
        float xw = k ? wx1 : wx0;
        int pk   = k ? pX : 1;
        // quad base: block(X(xc), Yb, Zb) + xbit*4
        float* Q = g_scratch
            + ((((size_t)(xc >> 1) & 127) * 128 + (size_t)(cy >> 1)) * 128 + (size_t)(cz >> 1)) * 8
            + (size_t)((xc & 1) << 2);
        red_v4p(Q,           xw * m00, xw * m01, xw * m10, xw * m11, pk);
        red_v4p(Q + SZ,      xw * n00, 0.0f,     xw * n10, 0.0f,     pk & pZ);
        red_v4p(Q + SY,      xw * q00, xw * q01, 0.0f,     0.0f,     pk & pY);
        red_v4p(Q + SY + SZ, xw * r00, 0.0f,     0.0f,     0.0f,     pk & pY & pZ);
    }
}

__global__ void __launch_bounds__(256, 8) cic_deposit_kernel(
    const float* __restrict__ pos,
    const float* __restrict__ wgt,
    int n)
{
    int t = blockIdx.x * blockDim.x + threadIdx.x;
    int base = 4 * t;
    if (base >= n) return;

    if (base + 3 < n) {
        const float4* p4 = (const float4*)pos + 3 * (size_t)t;
        float4 A = __ldcs(p4 + 0);
        float4 B = __ldcs(p4 + 1);
        float4 C = __ldcs(p4 + 2);
        float4 W = __ldcs((const float4*)wgt + t);

        deposit_one(A.x, A.y, A.z, W.x);
        deposit_one(A.w, B.x, B.y, W.y);
        deposit_one(B.z, B.w, C.x, W.z);
        deposit_one(C.y, C.z, C.w, W.w);
    } else {
        for (int i = base; i < n; i++) {
            float ppx = __ldcs(pos + 3 * (size_t)i + 0);
            float ppy = __ldcs(pos + 3 * (size_t)i + 1);
            float ppz = __ldcs(pos + 3 * (size_t)i + 2);
            float ww  = __ldcs(wgt + i);
            deposit_one(ppx, ppy, ppz, ww);
        }
    }
}

// depermute + rezero: thread b reads block (X,Y,Z), writes zeros back (keeps
// the scratch-is-zero invariant for the next graph replay), scatters 4
// coalesced float2 row-pairs into standard-layout out.
__global__ void __launch_bounds__(256) depermute_kernel(float* __restrict__ out, int nb) {
    int b = blockIdx.x * blockDim.x + threadIdx.x;
    if (b >= nb) return;
    int Z = b & 127;
    int Y = (b >> 7) & 127;
    int X = b >> 14;

    float4* blk = (float4*)(g_scratch + ((size_t)b << 3));
    float4 lo = blk[0];   // xbit=0: lanes (ybit,zbit) = 00,01,10,11
    float4 hi = blk[1];   // xbit=1
    blk[0] = make_float4(0.f, 0.f, 0.f, 0.f);
    blk[1] = make_float4(0.f, 0.f, 0.f, 0.f);

    float* r00 = out + (((size_t)(2 * X) * 256 + (size_t)(2 * Y)) * 256 + (size_t)(2 * Z));
    *(float2*)r00                 = make_float2(lo.x, lo.y);   // (x0,y0)
    *(float2*)(r00 + 256)         = make_float2(lo.z, lo.w);   // (x0,y1)
    *(float2*)(r00 + 65536)       = make_float2(hi.x, hi.y);   // (x1,y0)
    *(float2*)(r00 + 65536 + 256) = make_float2(hi.z, hi.w);   // (x1,y1)
}

extern "C" void kernel_launch(void* const* d_in, const int* in_sizes, int n_in,
                              void* d_out, int out_size) {
    const float* positions = (const float*)d_in[0];
    const float* weights   = (const float*)d_in[1];
    float* grid = (float*)d_out;

    int n_particles = in_sizes[1];  // weights element count = N

    // scratch is zero at entry: zero-initialized at module load, re-zeroed by
    // depermute_kernel on every prior execution.

    // 1) single-pass deposit, 4.5 active RED lanes/particle into 64MB scratch
    int n_threads_total = (n_particles + 3) / 4;
    int threads = 256;
    int blocks = (n_threads_total + threads - 1) / threads;
    cic_deposit_kernel<<<blocks, threads>>>(positions, weights, n_particles);

    // 2) depermute into d_out (fully overwrites it) + rezero scratch
    int nb = (int)NBLK;
    depermute_kernel<<<(nb + 255) / 256, 256>>>(grid, nb);
}

// round 13
// speedup vs baseline: 1.8930x; 1.6402x over previous
#include <cuda_runtime.h>
#include <cstdint>

// CIC deposition: 10M particles -> 256^3 float grid.
// Round 13: lane-pair sector coalescing test. 2x2x2-block permuted scratch
// (block = 32B sector, lane = xbit<<2|ybit<<1|zbit). Lanes (2k,2k+1) process
// the same particle (shfl width=2), lane h taking x-half h, so the particle's
// two x-half quads sit in the SAME RED instruction; when cx is even they are
// the two 16B halves of one 32B sector -> expected merge at L1tex/LTS.
// Expected sector-RMWs/particle: 2.25 * 1.5 = 3.375 (vs 4.5 unpaired).
// Overheads: plain zero kernel (12us) + R5-style gather depermute (28us).

static constexpr float GMINF = -10.0f;
static constexpr float DXF   = (float)(20.0 / 255.0);

static constexpr size_t NBLK = 128u * 128u * 128u;       // 2,097,152 blocks
__device__ __align__(32) float g_scratch[NBLK * 8];      // 64MB

__global__ void zero_scratch_kernel(int n4) {
    int i = blockIdx.x * blockDim.x + threadIdx.x;
    if (i < n4) ((float4*)g_scratch)[i] = make_float4(0.f, 0.f, 0.f, 0.f);
}

__device__ __forceinline__ void red_v4p(float* p, float a, float b, float c, float d, int pred) {
    asm volatile(
        "{\n\t"
        ".reg .pred q;\n\t"
        "setp.ne.s32 q, %5, 0;\n\t"
        "@q red.global.add.v4.f32 [%0], {%1, %2, %3, %4};\n\t"
        "}"
        :: "l"(p), "f"(a), "f"(b), "f"(c), "f"(d), "r"(pred) : "memory");
}

__global__ void __launch_bounds__(256) cic_deposit_kernel(
    const float* __restrict__ pos,
    const float* __restrict__ wgt,
    int n)
{
    int i    = blockIdx.x * blockDim.x + threadIdx.x;   // one particle per thread
    int lane = threadIdx.x & 31;
    int h    = lane & 1;                                 // x-half this lane owns

    // ---- load own particle & compute derived values ----
    float m00 = 0.f, m01 = 0.f, m10 = 0.f, m11 = 0.f;
    float n00 = 0.f, n10 = 0.f, q00 = 0.f, q01 = 0.f, r00 = 0.f;
    float xw0 = 0.f, xw1 = 0.f;
    int   B0 = 0, flags = 0;     // flags: bit0=valid, bit1=bx, bit2=pH1, bit3=pY, bit4=pZ

    if (i < n) {
        float px = __ldcs(pos + 3 * (size_t)i + 0);
        float py = __ldcs(pos + 3 * (size_t)i + 1);
        float pz = __ldcs(pos + 3 * (size_t)i + 2);
        float w  = __ldcs(wgt + i);

        // Match JAX float32 arithmetic: subtract then IEEE divide
        float fx = (px - GMINF) / DXF;
        float fy = (py - GMINF) / DXF;
        float fz = (pz - GMINF) / DXF;

        float ixf = floorf(fx), iyf = floorf(fy), izf = floorf(fz);
        int cx = (int)ixf, cy = (int)iyf, cz = (int)izf;

        if ((unsigned)cx <= 255u && (unsigned)cy <= 255u && (unsigned)cz <= 255u) {
            float ox = fx - ixf, oy = fy - iyf, oz = fz - izf;

            // corner weight = ((w * X) * Y) * Z (reference association)
            xw0 = w * (1.0f - ox);
            xw1 = w * ox;
            float wy0 = 1.0f - oy, wy1 = oy;
            float wz0 = 1.0f - oz, wz1 = oz;

            int bx = cx & 1, by = cy & 1, bz = cz & 1;

            float yw00 = by ? 0.0f : wy0, yw01 = by ? wy0 : wy1, yw10 = by ? wy1 : 0.0f;
            float zw00 = bz ? 0.0f : wz0, zw01 = bz ? wz0 : wz1, zw10 = bz ? wz1 : 0.0f;

            m00 = yw00 * zw00; m01 = yw00 * zw01; m10 = yw01 * zw00; m11 = yw01 * zw01;
            n00 = yw00 * zw10; n10 = yw01 * zw10;
            q00 = yw10 * zw00; q01 = yw10 * zw01;
            r00 = yw10 * zw10;

            int pH1 = bx ? (cx < 255) : 1;       // x-half 1 valid
            int pY  = by & (cy < 255);
            int pZ  = bz & (cz < 255);

            B0 = (((cx >> 1) * 128 + (cy >> 1)) * 128 + (cz >> 1));
            flags = 1 | (bx << 1) | (pH1 << 2) | (pY << 3) | (pZ << 4);
        }
    }

    // ---- two rounds: pair (2k,2k+1) processes particle of member r ----
    #pragma unroll
    for (int r = 0; r < 2; r++) {
        unsigned FULL = 0xffffffffu;
        float M00 = __shfl_sync(FULL, m00, r, 2);
        float M01 = __shfl_sync(FULL, m01, r, 2);
        float M10 = __shfl_sync(FULL, m10, r, 2);
        float M11 = __shfl_sync(FULL, m11, r, 2);
        float N00 = __shfl_sync(FULL, n00, r, 2);
        float N10 = __shfl_sync(FULL, n10, r, 2);
        float Q00 = __shfl_sync(FULL, q00, r, 2);
        float Q01 = __shfl_sync(FULL, q01, r, 2);
        float R00 = __shfl_sync(FULL, r00, r, 2);
        float XW0 = __shfl_sync(FULL, xw0, r, 2);
        float XW1 = __shfl_sync(FULL, xw1, r, 2);
        int   B   = __shfl_sync(FULL, B0,   r, 2);
        int   F   = __shfl_sync(FULL, flags, r, 2);

        int val = F & 1;
        int bx  = (F >> 1) & 1;
        int pH1 = (F >> 2) & 1;
        int PY  = (F >> 3) & 1;
        int PZ  = (F >> 4) & 1;

        float xw = h ? XW1 : XW0;
        // quad offset (floats): h=0 -> xbit(cx)=bx -> bx*4
        //                       h=1 -> bx ? block X+1 (+131072) : +4
        int off = h ? (bx ? 131072 : 4) : (bx << 2);
        int p0  = h ? (val & pH1) : val;

        float* A = g_scratch + ((size_t)(unsigned)B << 3) + (size_t)off;
        red_v4p(A,        xw * M00, xw * M01, xw * M10, xw * M11, p0);
        red_v4p(A + 8,    xw * N00, 0.0f,     xw * N10, 0.0f,     p0 & PZ);
        red_v4p(A + 1024, xw * Q00, xw * Q01, 0.0f,     0.0f,     p0 & PY);
        red_v4p(A + 1032, xw * R00, 0.0f,     0.0f,     0.0f,     p0 & PY & PZ);
    }
}

// depermute (R5-style, measured ~28us): thread t builds out float4 (4 z values)
// from fixed (xbit,ybit) float2 halves of two adjacent z-blocks.
__global__ void __launch_bounds__(256) depermute_kernel(float4* __restrict__ out, int n4) {
    int t = blockIdx.x * blockDim.x + threadIdx.x;
    if (t >= n4) return;
    int z4 = t & 63;          // z = 4*z4 .. 4*z4+3 -> z-blocks 2*z4, 2*z4+1
    int y  = (t >> 6) & 255;
    int x  = t >> 14;
    int X = x >> 1, Y = y >> 1;
    int off = ((x & 1) << 2) | ((y & 1) << 1);
    size_t bidx = (((size_t)X * 128 + (size_t)Y) * 128 + (size_t)(z4 << 1));
    const float* b0 = g_scratch + (bidx << 3) + off;
    float2 a = *(const float2*)b0;         // z-block 2z4:   z = 4z4, 4z4+1
    float2 b = *(const float2*)(b0 + 8);   // z-block 2z4+1: z = 4z4+2, 4z4+3
    out[t] = make_float4(a.x, a.y, b.x, b.y);
}

extern "C" void kernel_launch(void* const* d_in, const int* in_sizes, int n_in,
                              void* d_out, int out_size) {
    const float* positions = (const float*)d_in[0];
    const float* weights   = (const float*)d_in[1];
    float* grid = (float*)d_out;

    int n_particles = in_sizes[1];  // weights element count = N

    // 1) zero the 64MB permuted scratch
    int nz4 = (int)(NBLK * 8 / 4);
    zero_scratch_kernel<<<(nz4 + 255) / 256, 256>>>(nz4);

    // 2) lane-pair deposit: one particle per thread
    int threads = 256;
    int blocks = (n_particles + threads - 1) / threads;
    cic_deposit_kernel<<<blocks, threads>>>(positions, weights, n_particles);

    // 3) depermute into d_out (fully overwrites it)
    int n4 = out_size / 4;
    depermute_kernel<<<(n4 + 255) / 256, 256>>>((float4*)grid, n4);
}

// round 14
// speedup vs baseline: 2.0161x; 1.0650x over previous
#include <cuda_runtime.h>
#include <cstdint>

// CIC deposition: 10M particles -> 256^3 float grid.
// Round 14: 4-lane-group cooperation to test sector-vs-line cost granularity.
// 2x2x2-block permuted scratch (block = 32B sector, lane = xbit<<2|ybit<<1|zbit).
// Lane (h,s) of each 4-lane group takes x-half h and z-block s of the group's
// current particle, so ONE RED instruction covers all (x-half x z-block) quads
// (y-main); a second covers the y-spill row. 2 RED instructions/particle
// (R13: 4). Sectors/particle unchanged (3.375); distinct 128B lines ~2.53.
// If RMW cost is line-granular, deposit drops ~25%; if sector-granular, flat.

static constexpr float GMINF = -10.0f;
static constexpr float DXF   = (float)(20.0 / 255.0);

static constexpr size_t NBLK = 128u * 128u * 128u;       // 2,097,152 blocks
__device__ __align__(32) float g_scratch[NBLK * 8];      // 64MB

__global__ void zero_scratch_kernel(int n4) {
    int i = blockIdx.x * blockDim.x + threadIdx.x;
    if (i < n4) ((float4*)g_scratch)[i] = make_float4(0.f, 0.f, 0.f, 0.f);
}

__device__ __forceinline__ void red_v4p(float* p, float a, float b, float c, float d, int pred) {
    asm volatile(
        "{\n\t"
        ".reg .pred q;\n\t"
        "setp.ne.s32 q, %5, 0;\n\t"
        "@q red.global.add.v4.f32 [%0], {%1, %2, %3, %4};\n\t"
        "}"
        :: "l"(p), "f"(a), "f"(b), "f"(c), "f"(d), "r"(pred) : "memory");
}

__global__ void __launch_bounds__(256) cic_deposit_kernel(
    const float* __restrict__ pos,
    const float* __restrict__ wgt,
    int n)
{
    int i    = blockIdx.x * blockDim.x + threadIdx.x;   // one particle per thread
    int lane = threadIdx.x & 31;
    int h    = lane & 1;          // x-half this lane serves
    int s    = (lane >> 1) & 1;   // z-block this lane serves

    // ---- own particle -> derived values ----
    float xw0 = 0.f, xw1 = 0.f, oyv = 0.f, ozv = 0.f;
    int B = 0, fl = 0;   // fl: 1=valid | bx<<1 | by<<2 | bz<<3 | (cx<255)<<4 | (cy<255)<<5 | (cz<255)<<6

    if (i < n) {
        float px = __ldcs(pos + 3 * (size_t)i + 0);
        float py = __ldcs(pos + 3 * (size_t)i + 1);
        float pz = __ldcs(pos + 3 * (size_t)i + 2);
        float w  = __ldcs(wgt + i);

        // Match JAX float32 arithmetic: subtract then IEEE divide
        float fx = (px - GMINF) / DXF;
        float fy = (py - GMINF) / DXF;
        float fz = (pz - GMINF) / DXF;

        float ixf = floorf(fx), iyf = floorf(fy), izf = floorf(fz);
        int cx = (int)ixf, cy = (int)iyf, cz = (int)izf;

        if ((unsigned)cx <= 255u && (unsigned)cy <= 255u && (unsigned)cz <= 255u) {
            float ox = fx - ixf;
            oyv = fy - iyf;
            ozv = fz - izf;
            xw0 = w * (1.0f - ox);
            xw1 = w * ox;
            B = ((cx >> 1) * 128 + (cy >> 1)) * 128 + (cz >> 1);
            fl = 1 | ((cx & 1) << 1) | ((cy & 1) << 2) | ((cz & 1) << 3)
                   | ((int)(cx < 255) << 4) | ((int)(cy < 255) << 5) | ((int)(cz < 255) << 6);
        }
    }

    // ---- 4 rounds: group (4g..4g+3) processes member r's particle ----
    #pragma unroll
    for (int r = 0; r < 4; r++) {
        const unsigned FULL = 0xffffffffu;
        float XW0 = __shfl_sync(FULL, xw0, r, 4);
        float XW1 = __shfl_sync(FULL, xw1, r, 4);
        float OY  = __shfl_sync(FULL, oyv, r, 4);
        float OZ  = __shfl_sync(FULL, ozv, r, 4);
        int   Bb  = __shfl_sync(FULL, B,   r, 4);
        int   F   = __shfl_sync(FULL, fl,  r, 4);

        int val = F & 1;
        int bx = (F >> 1) & 1, by = (F >> 2) & 1, bz = (F >> 3) & 1;
        int lx = (F >> 4) & 1, ly = (F >> 5) & 1, lz = (F >> 6) & 1;

        float wy0 = 1.0f - OY, wy1 = OY;
        float wz0 = 1.0f - OZ, wz1 = OZ;

        // z values for this lane's z-block (lane order inside quad: ybit*2+zbit)
        float zv0 = s ? wz1 : (bz ? 0.0f : wz0);
        float zv1 = s ? 0.0f : (bz ? wz0 : wz1);
        float xw  = h ? XW1 : XW0;

        // y-main (block Y) lane weights per ybit
        float yA0 = by ? 0.0f : wy0;
        float yA1 = by ? wy0  : wy1;

        // lane address: x-half h=0 -> xbit=bx in block X; h=1 -> bx? block X+1
        // xbit0 : same block xbit1.  z-block offset s -> +8 floats.
        int xoff = h ? (bx ? 131072 : 4) : (bx << 2);   // floats; 131072 = 128*128*8
        float* Q = g_scratch + ((size_t)(unsigned)Bb << 3) + (size_t)(xoff + (s << 3));

        int pA = val & (h ? (bx ? lx : 1) : 1) & (s ? (bz & lz) : 1);
        red_v4p(Q, xw * (yA0 * zv0), xw * (yA0 * zv1),
                   xw * (yA1 * zv0), xw * (yA1 * zv1), pA);

        // y-spill (block Y+1, ybit0 = corner cy+1)
        int pB = pA & by & ly;
        red_v4p(Q + 1024, xw * (wy1 * zv0), xw * (wy1 * zv1), 0.0f, 0.0f, pB);
    }
}

// depermute (R5/R13-style): thread t builds out float4 (4 z values) from fixed
// (xbit,ybit) float2 halves of two adjacent z-blocks.
__global__ void __launch_bounds__(256) depermute_kernel(float4* __restrict__ out, int n4) {
    int t = blockIdx.x * blockDim.x + threadIdx.x;
    if (t >= n4) return;
    int z4 = t & 63;          // z = 4*z4 .. 4*z4+3 -> z-blocks 2*z4, 2*z4+1
    int y  = (t >> 6) & 255;
    int x  = t >> 14;
    int X = x >> 1, Y = y >> 1;
    int off = ((x & 1) << 2) | ((y & 1) << 1);
    size_t bidx = (((size_t)X * 128 + (size_t)Y) * 128 + (size_t)(z4 << 1));
    const float* b0 = g_scratch + (bidx << 3) + off;
    float2 a = *(const float2*)b0;         // z-block 2z4:   z = 4z4, 4z4+1
    float2 b = *(const float2*)(b0 + 8);   // z-block 2z4+1: z = 4z4+2, 4z4+3
    out[t] = make_float4(a.x, a.y, b.x, b.y);
}

extern "C" void kernel_launch(void* const* d_in, const int* in_sizes, int n_in,
                              void* d_out, int out_size) {
    const float* positions = (const float*)d_in[0];
    const float* weights   = (const float*)d_in[1];
    float* grid = (float*)d_out;

    int n_particles = in_sizes[1];  // weights element count = N

    // 1) zero the 64MB permuted scratch
    int nz4 = (int)(NBLK * 8 / 4);
    zero_scratch_kernel<<<(nz4 + 255) / 256, 256>>>(nz4);

    // 2) 4-lane-group deposit: one particle per thread
    int threads = 256;
    int blocks = (n_particles + threads - 1) / threads;
    cic_deposit_kernel<<<blocks, threads>>>(positions, weights, n_particles);

    // 3) depermute into d_out (fully overwrites it)
    int n4 = out_size / 4;
    depermute_kernel<<<(n4 + 255) / 256, 256>>>((float4*)grid, n4);
}